// round 1
// baseline (speedup 1.0000x reference)
#include <cuda_runtime.h>
#include <math.h>

// ---------------- problem constants ----------------
#define BB 64
#define TT 256
#define EE 300
#define HH 256
#define G4 1024          // 4*H
#define NLBL 17
#define LTOT 19
#define START_LBL 17
#define END_LBL 18
#define LOW_POT (-10000.0f)

// ---------------- device scratch ----------------
__device__ float g_xproj[(size_t)BB * TT * 2 * G4];   // [bt][2048] : fwd gates 0..1023, bwd 1024..2047 (bias included)
__device__ float g_hT[2][2][HH][BB];                  // [dir][buf][k=h-unit][b]  double-buffered recurrent state
__device__ float g_hall[(size_t)BB * TT * 2 * HH];    // [bt][512] : concat(h_f, h_b)
__device__ float g_unary[(size_t)BB * TT * NLBL];     // [bt][17]
__device__ unsigned g_bar[2];                         // per-direction step barrier counters

__device__ __forceinline__ float sigf(float x) { return 1.0f / (1.0f + expf(-x)); }

// ---------------- init: zero h-state + barriers ----------------
__global__ void k_init() {
    int i = blockIdx.x * blockDim.x + threadIdx.x;
    float* p = &g_hT[0][0][0][0];
    const int n = 2 * 2 * HH * BB;
    for (int l = i; l < n; l += gridDim.x * blockDim.x) p[l] = 0.0f;
    if (i < 2) g_bar[i] = 0u;
}

// ---------------- kernel 1: fused embedding gather + x_proj GEMM ----------------
// C[bt][g] = sum_k emb[x[bt]][k] * Wcat[g][k] + bcat[g]
// M=16384 (tiles of 128), N=2048 (tiles of 64), K=300 (tiles of 20, 300=15*20 exact)
__global__ void k_xproj(const int* __restrict__ x, const float* __restrict__ emb,
                        const float* __restrict__ Wf, const float* __restrict__ Wb,
                        const float* __restrict__ bf, const float* __restrict__ bb) {
    __shared__ float As[20][128];
    __shared__ float Bs[20][64];
    const int tid = threadIdx.x;
    const int m0 = blockIdx.y * 128;
    const int n0 = blockIdx.x * 64;
    const int tx = tid & 15;   // 16 col-groups of 4
    const int ty = tid >> 4;   // 16 row-groups of 8

    float acc[8][4];
#pragma unroll
    for (int i = 0; i < 8; i++)
#pragma unroll
        for (int j = 0; j < 4; j++) acc[i][j] = 0.0f;

    for (int k0 = 0; k0 < EE; k0 += 20) {
        // load A tile (gather embedding rows), store transposed [k][m]
        for (int l = tid; l < 128 * 20; l += 256) {
            int r = l / 20, k = l - r * 20;
            int tok = x[m0 + r];
            As[k][r] = emb[(size_t)tok * EE + k0 + k];
        }
        // load B tile [k][n]
        for (int l = tid; l < 64 * 20; l += 256) {
            int r = l / 20, k = l - r * 20;
            int g = n0 + r;
            Bs[k][r] = (g < G4) ? Wf[(size_t)g * EE + k0 + k]
                                : Wb[(size_t)(g - G4) * EE + k0 + k];
        }
        __syncthreads();
#pragma unroll
        for (int kk = 0; kk < 20; kk++) {
            float4 b4 = *(const float4*)&Bs[kk][tx * 4];
            float4 a0 = *(const float4*)&As[kk][ty * 8];
            float4 a1 = *(const float4*)&As[kk][ty * 8 + 4];
            float av[8] = {a0.x, a0.y, a0.z, a0.w, a1.x, a1.y, a1.z, a1.w};
            float bv[4] = {b4.x, b4.y, b4.z, b4.w};
#pragma unroll
            for (int i = 0; i < 8; i++)
#pragma unroll
                for (int j = 0; j < 4; j++) acc[i][j] += av[i] * bv[j];
        }
        __syncthreads();
    }

    // bias + store
    const int gc = n0 + tx * 4;
    float bias[4];
#pragma unroll
    for (int j = 0; j < 4; j++) {
        int g = gc + j;
        bias[j] = (g < G4) ? bf[g] : bb[g - G4];
    }
#pragma unroll
    for (int i = 0; i < 8; i++) {
        int row = m0 + ty * 8 + i;
        float4 v = make_float4(acc[i][0] + bias[0], acc[i][1] + bias[1],
                               acc[i][2] + bias[2], acc[i][3] + bias[3]);
        *(float4*)(&g_xproj[(size_t)row * 2048 + gc]) = v;
    }
}

// ---------------- kernel 2: persistent bidirectional LSTM ----------------
// 128 blocks: blocks [0..63] forward, [64..127] backward. Block j owns hidden
// units [4j, 4j+4) => 16 gate columns. Spin barrier per direction per step.
__global__ void k_lstm(const float* __restrict__ Whf, const float* __restrict__ Whb) {
    const int bid = blockIdx.x;
    const int d = bid >> 6;       // direction
    const int j = bid & 63;
    const int hu0 = j * 4;
    const int tid = threadIdx.x;

    __shared__ float Ws[HH * 17];      // [k][c] padded to 17 (conflict-free scalar reads)
    __shared__ float gs[4][BB][4];     // [gate s][b][q] raw pre-activations

    const float* Wh = d ? Whb : Whf;
    // load W_hh slice: Ws[k*17+c] = Wh[(s*256+hu0+q)*256 + k], c = s*4+q
    for (int l = tid; l < 16 * HH; l += 256) {
        int c = l >> 8;           // 0..15
        int k = l & 255;
        int s = c >> 2, q = c & 3;
        Ws[k * 17 + c] = Wh[(size_t)(s * HH + hu0 + q) * HH + k];
    }
    __syncthreads();

    // GEMM role: thread computes gates for 4 batches x 1 gate column
    const int c = tid & 15;
    const int b0 = (tid >> 4) * 4;
    const int s = c >> 2, q = c & 3;
    const int gcol = s * HH + hu0 + q;
    const float* xp = g_xproj + (size_t)d * G4 + gcol;

    // elementwise role (tid < 64): owns (4 batches, 1 hidden unit), c-state in regs
    const int eq = tid & 3;
    const int ebase = (tid >> 2) * 4;
    float creg[4] = {0.f, 0.f, 0.f, 0.f};

    for (int step = 0; step < TT; step++) {
        const int t = d ? (TT - 1 - step) : step;
        const float* hb = &g_hT[d][step & 1][0][0];
        float* hw = &g_hT[d][(step & 1) ^ 1][0][0];

        // init accumulators with x-projection (bias already folded in)
        float a0 = xp[((size_t)(b0 + 0) * TT + t) * 2048];
        float a1 = xp[((size_t)(b0 + 1) * TT + t) * 2048];
        float a2 = xp[((size_t)(b0 + 2) * TT + t) * 2048];
        float a3 = xp[((size_t)(b0 + 3) * TT + t) * 2048];

        // gate += h_prev . W_hh_row   (h read from L2, bypass L1)
#pragma unroll 4
        for (int k = 0; k < HH; k++) {
            float4 h4 = __ldcg((const float4*)(hb + k * BB + b0));
            float w = Ws[k * 17 + c];
            a0 += h4.x * w; a1 += h4.y * w; a2 += h4.z * w; a3 += h4.w * w;
        }
        gs[s][b0 + 0][q] = a0;
        gs[s][b0 + 1][q] = a1;
        gs[s][b0 + 2][q] = a2;
        gs[s][b0 + 3][q] = a3;
        __syncthreads();

        if (tid < 64) {
            float hv[4];
#pragma unroll
            for (int i = 0; i < 4; i++) {
                int b = ebase + i;
                float iv = gs[0][b][eq];
                float fv = gs[1][b][eq];
                float gv = gs[2][b][eq];
                float ov = gs[3][b][eq];
                float cc = sigf(fv) * creg[i] + sigf(iv) * tanhf(gv);
                creg[i] = cc;
                float hh = sigf(ov) * tanhf(cc);
                hv[i] = hh;
                g_hall[((size_t)b * TT + t) * 512 + d * HH + hu0 + eq] = hh;
            }
            *(float4*)(hw + (hu0 + eq) * BB + ebase) =
                make_float4(hv[0], hv[1], hv[2], hv[3]);
            __threadfence();   // make h writes visible at GPU scope before flag
        }
        __syncthreads();
        if (tid == 0) {
            atomicAdd(&g_bar[d], 1u);
            const unsigned target = (unsigned)(step + 1) * 64u;
            while (atomicAdd(&g_bar[d], 0u) < target) { }
        }
        __syncthreads();
    }
}

// ---------------- kernel 3: fused fc1(relu) + classifier ----------------
// per block: 64 rows.  inter = relu(h_all @ fc1_W.T + b) [64,128] -> unary [64,17]
__global__ void k_fc(const float* __restrict__ fc1W, const float* __restrict__ fc1b,
                     const float* __restrict__ clsW, const float* __restrict__ clsb) {
    __shared__ float As[16][64];
    __shared__ float Bs[16][128];
    __shared__ float inter[64][128];
    const int tid = threadIdx.x;
    const int m0 = blockIdx.x * 64;
    const int tr = tid >> 4;   // 16 row-groups of 4
    const int tc = tid & 15;   // 16 col-groups of 8

    float acc[4][8];
#pragma unroll
    for (int i = 0; i < 4; i++)
#pragma unroll
        for (int jj = 0; jj < 8; jj++) acc[i][jj] = 0.0f;

    for (int k0 = 0; k0 < 512; k0 += 16) {
        for (int l = tid; l < 64 * 16; l += 256) {
            int r = l >> 4, k = l & 15;
            As[k][r] = g_hall[(size_t)(m0 + r) * 512 + k0 + k];
        }
        for (int l = tid; l < 128 * 16; l += 256) {
            int n = l >> 4, k = l & 15;
            Bs[k][n] = fc1W[(size_t)n * 512 + k0 + k];
        }
        __syncthreads();
#pragma unroll
        for (int kk = 0; kk < 16; kk++) {
            float4 a = *(const float4*)&As[kk][tr * 4];
            float4 p = *(const float4*)&Bs[kk][tc * 8];
            float4 r = *(const float4*)&Bs[kk][tc * 8 + 4];
            float av[4] = {a.x, a.y, a.z, a.w};
            float bv[8] = {p.x, p.y, p.z, p.w, r.x, r.y, r.z, r.w};
#pragma unroll
            for (int i = 0; i < 4; i++)
#pragma unroll
                for (int jj = 0; jj < 8; jj++) acc[i][jj] += av[i] * bv[jj];
        }
        __syncthreads();
    }
#pragma unroll
    for (int i = 0; i < 4; i++) {
        int r = tr * 4 + i;
#pragma unroll
        for (int jj = 0; jj < 8; jj++) {
            int n = tc * 8 + jj;
            float v = acc[i][jj] + fc1b[n];
            inter[r][n] = v > 0.0f ? v : 0.0f;
        }
    }
    __syncthreads();

    for (int idx = tid; idx < 64 * NLBL; idx += 256) {
        int r = idx / NLBL, lab = idx - r * NLBL;
        float sacc = clsb[lab];
        const float* wrow = clsW + (size_t)lab * 128;
#pragma unroll 4
        for (int k = 0; k < 128; k++) sacc += inter[r][k] * wrow[k];
        g_unary[(size_t)(m0 + r) * NLBL + lab] = sacc;
    }
}

// ---------------- kernel 4: Viterbi decode, one block per batch ----------------
__global__ void k_viterbi(const float* __restrict__ trans, float* __restrict__ out) {
    const int b = blockIdx.x;
    const int tid = threadIdx.x;
    __shared__ float tr[LTOT * LTOT];
    __shared__ float sc[2][LTOT];
    __shared__ unsigned char bp[TT][LTOT];

    for (int l = tid; l < LTOT * LTOT; l += 32) tr[l] = trans[l];
    if (tid < LTOT) sc[0][tid] = (tid == START_LBL) ? 0.0f : LOW_POT;
    __syncwarp();

    const float* un = g_unary + (size_t)b * TT * NLBL;
    for (int t = 0; t < TT; t++) {
        const int cur = t & 1, nxt = cur ^ 1;
        if (tid < LTOT) {
            const int jl = tid;
            float best = -3.4e38f;
            int bi = 0;
#pragma unroll
            for (int p = 0; p < LTOT; p++) {
                float v = sc[cur][p] + tr[jl * LTOT + p];  // trans[next][prev]
                if (v > best) { best = v; bi = p; }
            }
            float u = (jl < NLBL) ? un[t * NLBL + jl] : LOW_POT;
            sc[nxt][jl] = best + u;
            bp[t][jl] = (unsigned char)bi;
        }
        __syncwarp();
    }
    if (tid == 0) {
        // after t=255, scores live in sc[0]
        float best = -3.4e38f;
        int bi = 0;
        for (int jl = 0; jl < LTOT; jl++) {
            float v = sc[0][jl] + tr[END_LBL * LTOT + jl];
            if (v > best) { best = v; bi = jl; }
        }
        out[b] = best;                       // path_score
        int lab = bi;
        for (int t = TT - 1; t >= 0; t--) {
            out[BB + b * TT + t] = (float)lab;
            lab = bp[t][lab];
        }
    }
}

// ---------------- launch ----------------
extern "C" void kernel_launch(void* const* d_in, const int* in_sizes, int n_in,
                              void* d_out, int out_size) {
    const int*   x     = (const int*)d_in[0];
    const float* emb   = (const float*)d_in[1];
    const float* Wihf  = (const float*)d_in[2];
    const float* Whhf  = (const float*)d_in[3];
    const float* bf    = (const float*)d_in[4];
    const float* Wihb  = (const float*)d_in[5];
    const float* Whhb  = (const float*)d_in[6];
    const float* bb    = (const float*)d_in[7];
    const float* fc1W  = (const float*)d_in[8];
    const float* fc1b  = (const float*)d_in[9];
    const float* clsW  = (const float*)d_in[10];
    const float* clsb  = (const float*)d_in[11];
    const float* trans = (const float*)d_in[12];
    float* out = (float*)d_out;

    k_init<<<32, 256>>>();
    k_xproj<<<dim3(32, 128), 256>>>(x, emb, Wihf, Wihb, bf, bb);
    k_lstm<<<128, 256>>>(Whhf, Whhb);
    k_fc<<<256, 256>>>(fc1W, fc1b, clsW, clsb);
    k_viterbi<<<BB, 32>>>(trans, out);
}

// round 2
// speedup vs baseline: 3.5335x; 3.5335x over previous
#include <cuda_runtime.h>
#include <math.h>

// ---------------- problem constants ----------------
#define BB 64
#define TT 256
#define EE 300
#define HH 256
#define G4 1024          // 4*H
#define NLBL 17
#define LTOT 19
#define START_LBL 17
#define END_LBL 18
#define LOW_POT (-10000.0f)

// ---------------- device scratch ----------------
__device__ float g_xproj[(size_t)BB * TT * 2 * G4];   // [bt][2048] fwd 0..1023, bwd 1024..2047 (bias folded)
__device__ float g_hT[2][2][HH][BB];                  // [dir][buf][k][b] double-buffered recurrent state
__device__ float g_hall[(size_t)BB * TT * 2 * HH];    // [bt][512] concat(h_f, h_b)
__device__ float g_unary[(size_t)BB * TT * NLBL];     // [bt][17]
__device__ unsigned g_bar[2];                         // per-direction step barrier counters

__device__ __forceinline__ float sigf(float x) { return 1.0f / (1.0f + expf(-x)); }

// ---------------- init ----------------
__global__ void k_init() {
    int i = blockIdx.x * blockDim.x + threadIdx.x;
    float* p = &g_hT[0][0][0][0];
    const int n = 2 * 2 * HH * BB;
    for (int l = i; l < n; l += gridDim.x * blockDim.x) p[l] = 0.0f;
    if (i < 2) g_bar[i] = 0u;
}

// ---------------- kernel 1: embedding gather + x_proj GEMM ----------------
// 128x128 tile, 8x8 micro-tile, k-tile 20 (300 = 15*20)
__global__ void k_xproj(const int* __restrict__ x, const float* __restrict__ emb,
                        const float* __restrict__ Wf, const float* __restrict__ Wb,
                        const float* __restrict__ bf, const float* __restrict__ bb) {
    __shared__ float As[20][128];
    __shared__ float Bs[20][128];
    __shared__ int toks[128];
    const int tid = threadIdx.x;
    const int m0 = blockIdx.y * 128;
    const int n0 = blockIdx.x * 128;
    const int tx = tid & 15;   // 16 col-groups of 8
    const int ty = tid >> 4;   // 16 row-groups of 8

    if (tid < 128) toks[tid] = x[m0 + tid];

    float acc[8][8];
#pragma unroll
    for (int i = 0; i < 8; i++)
#pragma unroll
        for (int j = 0; j < 8; j++) acc[i][j] = 0.0f;
    __syncthreads();

    for (int k0 = 0; k0 < EE; k0 += 20) {
        // A tile: gathered embedding rows, float4 loads, stored transposed [k][m]
#pragma unroll
        for (int l = tid; l < 640; l += 256) {
            int kq = l >> 7, r = l & 127;
            float4 v = *(const float4*)&emb[(size_t)toks[r] * EE + k0 + kq * 4];
            As[kq * 4 + 0][r] = v.x; As[kq * 4 + 1][r] = v.y;
            As[kq * 4 + 2][r] = v.z; As[kq * 4 + 3][r] = v.w;
        }
        // B tile: weight rows, float4 loads, stored transposed [k][n]
#pragma unroll
        for (int l = tid; l < 640; l += 256) {
            int kq = l >> 7, r = l & 127;
            int g = n0 + r;
            const float* Wp = (g < G4) ? &Wf[(size_t)g * EE] : &Wb[(size_t)(g - G4) * EE];
            float4 v = *(const float4*)&Wp[k0 + kq * 4];
            Bs[kq * 4 + 0][r] = v.x; Bs[kq * 4 + 1][r] = v.y;
            Bs[kq * 4 + 2][r] = v.z; Bs[kq * 4 + 3][r] = v.w;
        }
        __syncthreads();
#pragma unroll
        for (int kk = 0; kk < 20; kk++) {
            float4 a0 = *(const float4*)&As[kk][ty * 8];
            float4 a1 = *(const float4*)&As[kk][ty * 8 + 4];
            float4 p0 = *(const float4*)&Bs[kk][tx * 8];
            float4 p1 = *(const float4*)&Bs[kk][tx * 8 + 4];
            float av[8] = {a0.x, a0.y, a0.z, a0.w, a1.x, a1.y, a1.z, a1.w};
            float bv[8] = {p0.x, p0.y, p0.z, p0.w, p1.x, p1.y, p1.z, p1.w};
#pragma unroll
            for (int i = 0; i < 8; i++)
#pragma unroll
                for (int j = 0; j < 8; j++) acc[i][j] += av[i] * bv[j];
        }
        __syncthreads();
    }

    // bias + store
    const int gc = n0 + tx * 8;
    float bias[8];
#pragma unroll
    for (int j = 0; j < 8; j++) {
        int g = gc + j;
        bias[j] = (g < G4) ? bf[g] : bb[g - G4];
    }
#pragma unroll
    for (int i = 0; i < 8; i++) {
        int row = m0 + ty * 8 + i;
        float4 v0 = make_float4(acc[i][0] + bias[0], acc[i][1] + bias[1],
                                acc[i][2] + bias[2], acc[i][3] + bias[3]);
        float4 v1 = make_float4(acc[i][4] + bias[4], acc[i][5] + bias[5],
                                acc[i][6] + bias[6], acc[i][7] + bias[7]);
        *(float4*)(&g_xproj[(size_t)row * 2048 + gc]) = v0;
        *(float4*)(&g_xproj[(size_t)row * 2048 + gc + 4]) = v1;
    }
}

// ---------------- kernel 2: persistent bidirectional LSTM ----------------
// 128 blocks: [0..63] fwd, [64..127] bwd. Block j owns hidden units [4j,4j+4).
// h_prev staged into SMEM each step; elementwise spread over all 256 threads.
#define LSTM_SMEM_FLOATS (4384 + 16384 + 1024)
__global__ void k_lstm(const float* __restrict__ Whf, const float* __restrict__ Whb) {
    extern __shared__ float sm[];
    float* Ws = sm;              // [k*17 + c], 4352 used (pad 4384)
    float* hs = sm + 4384;       // [k][b] 256x64
    float* gs = sm + 4384 + 16384; // [s][b][q] 4*64*4

    const int bid = blockIdx.x;
    const int d = bid >> 6;
    const int j = bid & 63;
    const int hu0 = j * 4;
    const int tid = threadIdx.x;

    const float* Wh = d ? Whb : Whf;
    // Ws[k*17+c] = Wh[(s*256+hu0+q)*256 + k], c = s*4+q
#pragma unroll
    for (int l = tid; l < 16 * HH; l += 256) {
        int c = l >> 8;
        int k = l & 255;
        int s = c >> 2, q = c & 3;
        Ws[k * 17 + c] = Wh[(size_t)(s * HH + hu0 + q) * HH + k];
    }
    __syncthreads();

    // GEMV role: (col c, 4 batches b0..b0+3)
    const int c = tid & 15;
    const int b0 = (tid >> 4) * 4;
    const int s = c >> 2, q = c & 3;
    const int gcol = s * HH + hu0 + q;
    const float* xp = g_xproj + (size_t)d * G4 + gcol;

    // elementwise role: one (batch, unit) pair per thread
    const int eb = tid & 63;
    const int eu = tid >> 6;
    float creg = 0.0f;

    unsigned target = 0;
    for (int step = 0; step < TT; step++) {
        const int t = d ? (TT - 1 - step) : step;
        const float* hb = &g_hT[d][step & 1][0][0];
        float* hw = &g_hT[d][(step & 1) ^ 1][0][0];

        // x-projection init (issue early, L2 latency overlaps the h fill)
        float a0 = __ldcg(&xp[((size_t)(b0 + 0) * TT + t) * 2048]);
        float a1 = __ldcg(&xp[((size_t)(b0 + 1) * TT + t) * 2048]);
        float a2 = __ldcg(&xp[((size_t)(b0 + 2) * TT + t) * 2048]);
        float a3 = __ldcg(&xp[((size_t)(b0 + 3) * TT + t) * 2048]);

        // stage h_prev into SMEM (coalesced, one copy per block)
        const float4* hb4 = (const float4*)hb;
        float4* hs4 = (float4*)hs;
#pragma unroll
        for (int l = tid; l < 4096; l += 256) hs4[l] = __ldcg(hb4 + l);
        __syncthreads();

        // GEMV from SMEM
#pragma unroll 8
        for (int k = 0; k < HH; k++) {
            float4 h4 = *(const float4*)(hs + k * BB + b0);
            float w = Ws[k * 17 + c];
            a0 += h4.x * w; a1 += h4.y * w; a2 += h4.z * w; a3 += h4.w * w;
        }
        gs[s * 256 + (b0 + 0) * 4 + q] = a0;
        gs[s * 256 + (b0 + 1) * 4 + q] = a1;
        gs[s * 256 + (b0 + 2) * 4 + q] = a2;
        gs[s * 256 + (b0 + 3) * 4 + q] = a3;
        __syncthreads();

        // elementwise: all 256 threads, one (b,u) each
        {
            float iv = gs[0 * 256 + eb * 4 + eu];
            float fv = gs[1 * 256 + eb * 4 + eu];
            float gv = gs[2 * 256 + eb * 4 + eu];
            float ov = gs[3 * 256 + eb * 4 + eu];
            float cc = sigf(fv) * creg + sigf(iv) * tanhf(gv);
            creg = cc;
            float hh = sigf(ov) * tanhf(cc);
            hw[(hu0 + eu) * BB + eb] = hh;
            g_hall[((size_t)eb * TT + t) * 512 + d * HH + hu0 + eu] = hh;
        }
        __threadfence();
        __syncthreads();

        // inter-block barrier: atomic arrive, volatile-load poll
        target += 64;
        if (tid == 0) {
            atomicAdd(&g_bar[d], 1u);
            volatile unsigned* f = &g_bar[d];
            while (*f < target) { }
            __threadfence();
        }
        __syncthreads();
    }
}

// ---------------- kernel 3: fused fc1(relu) + classifier ----------------
// 128 rows per block, N=128 (single n-tile), K=512, k-tile 16, 8x8 micro-tile
#define FC_SMEM_FLOATS (128 * 129)
__global__ void k_fc(const float* __restrict__ fc1W, const float* __restrict__ fc1b,
                     const float* __restrict__ clsW, const float* __restrict__ clsb) {
    __shared__ float As[16][128];
    __shared__ float Bs[16][128];
    extern __shared__ float inter[];   // [128][129]
    const int tid = threadIdx.x;
    const int m0 = blockIdx.x * 128;
    const int tr = tid >> 4;   // 16 row-groups of 8
    const int tc = tid & 15;   // 16 col-groups of 8

    float acc[8][8];
#pragma unroll
    for (int i = 0; i < 8; i++)
#pragma unroll
        for (int jj = 0; jj < 8; jj++) acc[i][jj] = 0.0f;

    for (int k0 = 0; k0 < 512; k0 += 16) {
#pragma unroll
        for (int l = tid; l < 512; l += 256) {
            int kq = l >> 7, r = l & 127;
            float4 v = *(const float4*)&g_hall[(size_t)(m0 + r) * 512 + k0 + kq * 4];
            As[kq * 4 + 0][r] = v.x; As[kq * 4 + 1][r] = v.y;
            As[kq * 4 + 2][r] = v.z; As[kq * 4 + 3][r] = v.w;
        }
#pragma unroll
        for (int l = tid; l < 512; l += 256) {
            int kq = l >> 7, r = l & 127;
            float4 v = *(const float4*)&fc1W[(size_t)r * 512 + k0 + kq * 4];
            Bs[kq * 4 + 0][r] = v.x; Bs[kq * 4 + 1][r] = v.y;
            Bs[kq * 4 + 2][r] = v.z; Bs[kq * 4 + 3][r] = v.w;
        }
        __syncthreads();
#pragma unroll
        for (int kk = 0; kk < 16; kk++) {
            float4 a0 = *(const float4*)&As[kk][tr * 8];
            float4 a1 = *(const float4*)&As[kk][tr * 8 + 4];
            float4 p0 = *(const float4*)&Bs[kk][tc * 8];
            float4 p1 = *(const float4*)&Bs[kk][tc * 8 + 4];
            float av[8] = {a0.x, a0.y, a0.z, a0.w, a1.x, a1.y, a1.z, a1.w};
            float bv[8] = {p0.x, p0.y, p0.z, p0.w, p1.x, p1.y, p1.z, p1.w};
#pragma unroll
            for (int i = 0; i < 8; i++)
#pragma unroll
                for (int jj = 0; jj < 8; jj++) acc[i][jj] += av[i] * bv[jj];
        }
        __syncthreads();
    }
    // relu + bias -> inter (padded rows of 129 for conflict-free column reads)
#pragma unroll
    for (int i = 0; i < 8; i++) {
        int r = tr * 8 + i;
#pragma unroll
        for (int jj = 0; jj < 8; jj++) {
            int n = tc * 8 + jj;
            float v = acc[i][jj] + fc1b[n];
            inter[r * 129 + n] = v > 0.0f ? v : 0.0f;
        }
    }
    __syncthreads();

    // classifier: 128 rows x 17 labels
    for (int idx = tid; idx < 128 * NLBL; idx += 256) {
        int r = idx / NLBL, lab = idx - r * NLBL;
        float sacc = clsb[lab];
        const float* wrow = clsW + (size_t)lab * 128;
#pragma unroll 8
        for (int k = 0; k < 128; k++) sacc += inter[r * 129 + k] * wrow[k];
        g_unary[(size_t)(m0 + r) * NLBL + lab] = sacc;
    }
}

// ---------------- kernel 4: Viterbi decode, one block per batch ----------------
__global__ void k_viterbi(const float* __restrict__ trans, float* __restrict__ out) {
    const int b = blockIdx.x;
    const int tid = threadIdx.x;
    __shared__ float tr[LTOT * LTOT];
    __shared__ float sc[2][LTOT];
    __shared__ unsigned char bp[TT][LTOT];

    for (int l = tid; l < LTOT * LTOT; l += 32) tr[l] = trans[l];
    if (tid < LTOT) sc[0][tid] = (tid == START_LBL) ? 0.0f : LOW_POT;
    __syncwarp();

    const float* un = g_unary + (size_t)b * TT * NLBL;
    for (int t = 0; t < TT; t++) {
        const int cur = t & 1, nxt = cur ^ 1;
        if (tid < LTOT) {
            const int jl = tid;
            float best = -3.4e38f;
            int bi = 0;
#pragma unroll
            for (int p = 0; p < LTOT; p++) {
                float v = sc[cur][p] + tr[jl * LTOT + p];
                if (v > best) { best = v; bi = p; }
            }
            float u = (jl < NLBL) ? un[t * NLBL + jl] : LOW_POT;
            sc[nxt][jl] = best + u;
            bp[t][jl] = (unsigned char)bi;
        }
        __syncwarp();
    }
    if (tid == 0) {
        float best = -3.4e38f;
        int bi = 0;
        for (int jl = 0; jl < LTOT; jl++) {
            float v = sc[0][jl] + tr[END_LBL * LTOT + jl];
            if (v > best) { best = v; bi = jl; }
        }
        out[b] = best;
        int lab = bi;
        for (int t = TT - 1; t >= 0; t--) {
            out[BB + b * TT + t] = (float)lab;
            lab = bp[t][lab];
        }
    }
}

// ---------------- launch ----------------
extern "C" void kernel_launch(void* const* d_in, const int* in_sizes, int n_in,
                              void* d_out, int out_size) {
    const int*   x     = (const int*)d_in[0];
    const float* emb   = (const float*)d_in[1];
    const float* Wihf  = (const float*)d_in[2];
    const float* Whhf  = (const float*)d_in[3];
    const float* bf    = (const float*)d_in[4];
    const float* Wihb  = (const float*)d_in[5];
    const float* Whhb  = (const float*)d_in[6];
    const float* bb    = (const float*)d_in[7];
    const float* fc1W  = (const float*)d_in[8];
    const float* fc1b  = (const float*)d_in[9];
    const float* clsW  = (const float*)d_in[10];
    const float* clsb  = (const float*)d_in[11];
    const float* trans = (const float*)d_in[12];
    float* out = (float*)d_out;

    cudaFuncSetAttribute(k_lstm, cudaFuncAttributeMaxDynamicSharedMemorySize,
                         LSTM_SMEM_FLOATS * sizeof(float));
    cudaFuncSetAttribute(k_fc, cudaFuncAttributeMaxDynamicSharedMemorySize,
                         FC_SMEM_FLOATS * sizeof(float));

    k_init<<<32, 256>>>();
    k_xproj<<<dim3(16, 128), 256>>>(x, emb, Wihf, Wihb, bf, bb);
    k_lstm<<<128, 256, LSTM_SMEM_FLOATS * sizeof(float)>>>(Whhf, Whhb);
    k_fc<<<128, 256, FC_SMEM_FLOATS * sizeof(float)>>>(fc1W, fc1b, clsW, clsb);
    k_viterbi<<<BB, 32>>>(trans, out);
}

// round 4
// speedup vs baseline: 4.2472x; 1.2020x over previous
#include <cuda_runtime.h>
#include <math.h>

// ---------------- problem constants ----------------
#define BB 64
#define TT 256
#define EE 300
#define HH 256
#define G4 1024          // 4*H
#define NLBL 17
#define LTOT 19
#define START_LBL 17
#define END_LBL 18
#define LOW_POT (-10000.0f)

typedef unsigned long long u64;

// ---------------- packed f32x2 helpers (Blackwell, .b64 regs) ----------------
__device__ __forceinline__ u64 fdup(float x) {
    u64 r; asm("mov.b64 %0,{%1,%1};" : "=l"(r) : "f"(x)); return r;
}
__device__ __forceinline__ void fma2(u64& a, u64 m, u64 b) {
    asm("fma.rn.f32x2 %0,%1,%2,%0;" : "+l"(a) : "l"(m), "l"(b));
}
__device__ __forceinline__ void add2(u64& a, u64 b) {
    asm("add.rn.f32x2 %0,%0,%1;" : "+l"(a) : "l"(b));
}
__device__ __forceinline__ float2 f2lo(u64 v) {
    float2 r; asm("mov.b64 {%0,%1},%2;" : "=f"(r.x), "=f"(r.y) : "l"(v)); return r;
}

// ---------------- device scratch ----------------
__device__ float g_xproj[(size_t)BB * TT * 2 * G4];   // [bt][2048] fwd 0..1023, bwd 1024..2047 (bias folded)
__device__ float g_hT[2][2][HH][BB];                  // [dir][buf][k][b] double-buffered recurrent state
__device__ float g_hall[(size_t)BB * TT * 2 * HH];    // [bt][512] concat(h_f, h_b)
__device__ float g_unary[(size_t)BB * TT * NLBL];     // [bt][17]
__device__ unsigned g_bar[2];                         // per-direction step barrier counters

__device__ __forceinline__ float sigf(float x) { return 1.0f / (1.0f + expf(-x)); }

// ---------------- init ----------------
__global__ void k_init() {
    int i = blockIdx.x * blockDim.x + threadIdx.x;
    float* p = &g_hT[0][0][0][0];
    const int n = 2 * 2 * HH * BB;
    for (int l = i; l < n; l += gridDim.x * blockDim.x) p[l] = 0.0f;
    if (i < 2) g_bar[i] = 0u;
}

// ---------------- kernel 1: embedding gather + x_proj GEMM ----------------
// 128x128 tile, 8x8 micro-tile via f32x2, k-tile 20 (300 = 15*20)
__global__ void k_xproj(const int* __restrict__ x, const float* __restrict__ emb,
                        const float* __restrict__ Wf, const float* __restrict__ Wb,
                        const float* __restrict__ bf, const float* __restrict__ bb) {
    __shared__ float As[20][128];
    __shared__ float Bs[20][128];
    __shared__ int toks[128];
    const int tid = threadIdx.x;
    const int m0 = blockIdx.y * 128;
    const int n0 = blockIdx.x * 128;
    const int tx = tid & 15;   // 16 col-groups of 8
    const int ty = tid >> 4;   // 16 row-groups of 8

    if (tid < 128) toks[tid] = x[m0 + tid];

    u64 acc2[8][4];
#pragma unroll
    for (int i = 0; i < 8; i++)
#pragma unroll
        for (int j = 0; j < 4; j++) acc2[i][j] = 0ull;
    __syncthreads();

    for (int k0 = 0; k0 < EE; k0 += 20) {
#pragma unroll
        for (int l = tid; l < 640; l += 256) {
            int kq = l >> 7, r = l & 127;
            float4 v = *(const float4*)&emb[(size_t)toks[r] * EE + k0 + kq * 4];
            As[kq * 4 + 0][r] = v.x; As[kq * 4 + 1][r] = v.y;
            As[kq * 4 + 2][r] = v.z; As[kq * 4 + 3][r] = v.w;
        }
#pragma unroll
        for (int l = tid; l < 640; l += 256) {
            int kq = l >> 7, r = l & 127;
            int g = n0 + r;
            const float* Wp = (g < G4) ? &Wf[(size_t)g * EE] : &Wb[(size_t)(g - G4) * EE];
            float4 v = *(const float4*)&Wp[k0 + kq * 4];
            Bs[kq * 4 + 0][r] = v.x; Bs[kq * 4 + 1][r] = v.y;
            Bs[kq * 4 + 2][r] = v.z; Bs[kq * 4 + 3][r] = v.w;
        }
        __syncthreads();
#pragma unroll
        for (int kk = 0; kk < 20; kk++) {
            float4 a0 = *(const float4*)&As[kk][ty * 8];
            float4 a1 = *(const float4*)&As[kk][ty * 8 + 4];
            ulonglong2 b01 = *(const ulonglong2*)&Bs[kk][tx * 8];
            ulonglong2 b23 = *(const ulonglong2*)&Bs[kk][tx * 8 + 4];
            float av[8] = {a0.x, a0.y, a0.z, a0.w, a1.x, a1.y, a1.z, a1.w};
#pragma unroll
            for (int i = 0; i < 8; i++) {
                u64 ad = fdup(av[i]);
                fma2(acc2[i][0], ad, b01.x);
                fma2(acc2[i][1], ad, b01.y);
                fma2(acc2[i][2], ad, b23.x);
                fma2(acc2[i][3], ad, b23.y);
            }
        }
        __syncthreads();
    }

    // bias + store
    const int gc = n0 + tx * 8;
    float bias[8];
#pragma unroll
    for (int j = 0; j < 8; j++) {
        int g = gc + j;
        bias[j] = (g < G4) ? bf[g] : bb[g - G4];
    }
#pragma unroll
    for (int i = 0; i < 8; i++) {
        int row = m0 + ty * 8 + i;
        float2 p0 = f2lo(acc2[i][0]);
        float2 p1 = f2lo(acc2[i][1]);
        float2 p2 = f2lo(acc2[i][2]);
        float2 p3 = f2lo(acc2[i][3]);
        float4 v0 = make_float4(p0.x + bias[0], p0.y + bias[1], p1.x + bias[2], p1.y + bias[3]);
        float4 v1 = make_float4(p2.x + bias[4], p2.y + bias[5], p3.x + bias[6], p3.y + bias[7]);
        *(float4*)(&g_xproj[(size_t)row * 2048 + gc]) = v0;
        *(float4*)(&g_xproj[(size_t)row * 2048 + gc + 4]) = v1;
    }
}

// ---------------- kernel 2: persistent bidirectional LSTM ----------------
// 128 blocks: [0..63] fwd, [64..127] bwd. Block j owns hidden units [4j,4j+4)
// (16 gate columns x 64 batches = 1024 outputs per step).
// GEMV: 8 warps = 8 k-groups (k-range 32). Each lane: 8 batches x 4 cols
// micro-tile with packed f32x2 FMA. Partials reduced in SMEM with add.f32x2.
#define LSTM_SMEM_FLOATS (4096 + 16384 + 8192 + 1024)
__global__ void k_lstm(const float* __restrict__ Whf, const float* __restrict__ Whb) {
    extern __shared__ float sm[];
    float* Ws2 = sm;                        // [k][16]      4096 floats
    float* hs  = sm + 4096;                 // [k][64]      16384 floats
    u64*   red = (u64*)(sm + 4096 + 16384); // [8][512] u64 (8192 floats)
    float* gs  = sm + 4096 + 16384 + 8192;  // [s][64][4]   1024 floats

    const int bid = blockIdx.x;
    const int d = bid >> 6;
    const int j = bid & 63;
    const int hu0 = j * 4;
    const int tid = threadIdx.x;
    const float* Wh = d ? Whb : Whf;

    // Ws2[k*16+c] = Wh[(s*256+hu0+q)*256 + k], c = s*4+q  (coalesced over k)
#pragma unroll
    for (int l = tid; l < 4096; l += 256) {
        int c = l >> 8;
        int k = l & 255;
        int s = c >> 2, q = c & 3;
        Ws2[k * 16 + c] = Wh[(size_t)(s * HH + hu0 + q) * HH + k];
    }

    // GEMV roles
    const int kg = tid >> 5;       // warp = k-group
    const int wi = tid & 31;
    const int c4 = (wi & 3) * 4;   // 4 cols
    const int b8 = (wi >> 2) * 8;  // 8 batches
    const int kbeg = kg * 32;

    // reducer roles: 2 packed outputs (c, batch-pair) per thread
    const int oid0 = tid * 2, oid1 = tid * 2 + 1;
    const int rc0 = oid0 >> 5, rb0 = (oid0 & 31) * 2;
    const int rc1 = oid1 >> 5, rb1 = (oid1 & 31) * 2;
    const size_t xcol0 = (size_t)d * G4 + (size_t)(rc0 >> 2) * HH + hu0 + (rc0 & 3);
    const size_t xcol1 = (size_t)d * G4 + (size_t)(rc1 >> 2) * HH + hu0 + (rc1 & 3);
    const int g0 = (rc0 >> 2) * 256 + (rc0 & 3);
    const int g1 = (rc1 >> 2) * 256 + (rc1 & 3);

    // elementwise role: one (batch, unit)
    const int eb = tid & 63;
    const int eu = tid >> 6;
    float creg = 0.0f;
    __syncthreads();

    unsigned target = 0;
    for (int step = 0; step < TT; step++) {
        const int t = d ? (TT - 1 - step) : step;
        const float* hb = &g_hT[d][step & 1][0][0];
        float* hw = &g_hT[d][(step & 1) ^ 1][0][0];

        // x-projection values for this thread's reduced outputs (issue early)
        float x00 = __ldcg(&g_xproj[((size_t)(rb0 + 0) * TT + t) * 2048 + xcol0]);
        float x01 = __ldcg(&g_xproj[((size_t)(rb0 + 1) * TT + t) * 2048 + xcol0]);
        float x10 = __ldcg(&g_xproj[((size_t)(rb1 + 0) * TT + t) * 2048 + xcol1]);
        float x11 = __ldcg(&g_xproj[((size_t)(rb1 + 1) * TT + t) * 2048 + xcol1]);

        // stage h_prev into SMEM
        {
            const float4* hb4 = (const float4*)hb;
            float4* hs4 = (float4*)hs;
#pragma unroll
            for (int l = tid; l < 4096; l += 256) hs4[l] = __ldcg(hb4 + l);
        }
        __syncthreads();

        // GEMV partial over this warp's k range: 8 batches x 4 cols
        u64 acc2[4][4];
#pragma unroll
        for (int bp = 0; bp < 4; bp++)
#pragma unroll
            for (int ci = 0; ci < 4; ci++) acc2[bp][ci] = 0ull;
#pragma unroll 4
        for (int k = kbeg; k < kbeg + 32; k++) {
            ulonglong2 h01 = *(const ulonglong2*)&hs[k * 64 + b8];
            ulonglong2 h23 = *(const ulonglong2*)&hs[k * 64 + b8 + 4];
            float4 w4 = *(const float4*)&Ws2[k * 16 + c4];
            u64 w0 = fdup(w4.x), w1 = fdup(w4.y), w2 = fdup(w4.z), w3 = fdup(w4.w);
            fma2(acc2[0][0], h01.x, w0); fma2(acc2[0][1], h01.x, w1);
            fma2(acc2[0][2], h01.x, w2); fma2(acc2[0][3], h01.x, w3);
            fma2(acc2[1][0], h01.y, w0); fma2(acc2[1][1], h01.y, w1);
            fma2(acc2[1][2], h01.y, w2); fma2(acc2[1][3], h01.y, w3);
            fma2(acc2[2][0], h23.x, w0); fma2(acc2[2][1], h23.x, w1);
            fma2(acc2[2][2], h23.x, w2); fma2(acc2[2][3], h23.x, w3);
            fma2(acc2[3][0], h23.y, w0); fma2(acc2[3][1], h23.y, w1);
            fma2(acc2[3][2], h23.y, w2); fma2(acc2[3][3], h23.y, w3);
        }
        // partials: red[kg][c][bpair]
#pragma unroll
        for (int ci = 0; ci < 4; ci++)
#pragma unroll
            for (int bp = 0; bp < 4; bp++)
                red[kg * 512 + (c4 + ci) * 32 + (b8 >> 1) + bp] = acc2[bp][ci];
        __syncthreads();

        // reduce 8 partials + add x-projection -> gate values in gs
        {
            u64 s0 = red[oid0];
            u64 s1 = red[oid1];
#pragma unroll
            for (int g2 = 1; g2 < 8; g2++) {
                add2(s0, red[g2 * 512 + oid0]);
                add2(s1, red[g2 * 512 + oid1]);
            }
            float2 f0 = f2lo(s0), f1 = f2lo(s1);
            gs[g0 + (rb0 + 0) * 4] = f0.x + x00;
            gs[g0 + (rb0 + 1) * 4] = f0.y + x01;
            gs[g1 + (rb1 + 0) * 4] = f1.x + x10;
            gs[g1 + (rb1 + 1) * 4] = f1.y + x11;
        }
        __syncthreads();

        // elementwise LSTM cell
        {
            float iv = gs[0 * 256 + eb * 4 + eu];
            float fv = gs[1 * 256 + eb * 4 + eu];
            float gv = gs[2 * 256 + eb * 4 + eu];
            float ov = gs[3 * 256 + eb * 4 + eu];
            float cc = sigf(fv) * creg + sigf(iv) * tanhf(gv);
            creg = cc;
            float hh = sigf(ov) * tanhf(cc);
            hw[(hu0 + eu) * BB + eb] = hh;
            g_hall[((size_t)eb * TT + t) * 512 + d * HH + hu0 + eu] = hh;
        }
        __syncthreads();

        // inter-block barrier
        target += 64;
        if (tid == 0) {
            __threadfence();
            atomicAdd(&g_bar[d], 1u);
            volatile unsigned* f = &g_bar[d];
            while (*f < target) { }
            __threadfence();
        }
        __syncthreads();
    }
}

// ---------------- kernel 3: fused fc1(relu) + classifier ----------------
#define FC_SMEM_FLOATS (128 * 130)
__global__ void k_fc(const float* __restrict__ fc1W, const float* __restrict__ fc1b,
                     const float* __restrict__ clsW, const float* __restrict__ clsb) {
    __shared__ float As[16][128];
    __shared__ float Bs[16][128];
    extern __shared__ float inter[];   // [128][130]
    const int tid = threadIdx.x;
    const int m0 = blockIdx.x * 128;
    const int tr = tid >> 4;
    const int tc = tid & 15;

    u64 acc2[8][4];
#pragma unroll
    for (int i = 0; i < 8; i++)
#pragma unroll
        for (int jj = 0; jj < 4; jj++) acc2[i][jj] = 0ull;

    for (int k0 = 0; k0 < 512; k0 += 16) {
#pragma unroll
        for (int l = tid; l < 512; l += 256) {
            int kq = l >> 7, r = l & 127;
            float4 v = *(const float4*)&g_hall[(size_t)(m0 + r) * 512 + k0 + kq * 4];
            As[kq * 4 + 0][r] = v.x; As[kq * 4 + 1][r] = v.y;
            As[kq * 4 + 2][r] = v.z; As[kq * 4 + 3][r] = v.w;
        }
#pragma unroll
        for (int l = tid; l < 512; l += 256) {
            int kq = l >> 7, r = l & 127;
            float4 v = *(const float4*)&fc1W[(size_t)r * 512 + k0 + kq * 4];
            Bs[kq * 4 + 0][r] = v.x; Bs[kq * 4 + 1][r] = v.y;
            Bs[kq * 4 + 2][r] = v.z; Bs[kq * 4 + 3][r] = v.w;
        }
        __syncthreads();
#pragma unroll
        for (int kk = 0; kk < 16; kk++) {
            float4 a0 = *(const float4*)&As[kk][tr * 8];
            float4 a1 = *(const float4*)&As[kk][tr * 8 + 4];
            ulonglong2 b01 = *(const ulonglong2*)&Bs[kk][tc * 8];
            ulonglong2 b23 = *(const ulonglong2*)&Bs[kk][tc * 8 + 4];
            float av[8] = {a0.x, a0.y, a0.z, a0.w, a1.x, a1.y, a1.z, a1.w};
#pragma unroll
            for (int i = 0; i < 8; i++) {
                u64 ad = fdup(av[i]);
                fma2(acc2[i][0], ad, b01.x);
                fma2(acc2[i][1], ad, b01.y);
                fma2(acc2[i][2], ad, b23.x);
                fma2(acc2[i][3], ad, b23.y);
            }
        }
        __syncthreads();
    }
    // relu + bias -> inter (rows padded to 130 floats: 8B-aligned rows)
#pragma unroll
    for (int i = 0; i < 8; i++) {
        int r = tr * 8 + i;
#pragma unroll
        for (int jj = 0; jj < 4; jj++) {
            int n = tc * 8 + jj * 2;
            float2 p = f2lo(acc2[i][jj]);
            float v0 = p.x + fc1b[n];
            float v1 = p.y + fc1b[n + 1];
            inter[r * 130 + n]     = v0 > 0.0f ? v0 : 0.0f;
            inter[r * 130 + n + 1] = v1 > 0.0f ? v1 : 0.0f;
        }
    }
    __syncthreads();

    // classifier: 128 rows x 17 labels, packed dot products
    for (int idx = tid; idx < 128 * NLBL; idx += 256) {
        int r = idx / NLBL, lab = idx - r * NLBL;
        const u64* w2 = (const u64*)(clsW + (size_t)lab * 128);
        const u64* i2 = (const u64*)(inter + r * 130);
        u64 s2 = 0ull;
#pragma unroll 8
        for (int k = 0; k < 64; k++) fma2(s2, i2[k], w2[k]);
        float2 p = f2lo(s2);
        g_unary[(size_t)(m0 + r) * NLBL + lab] = clsb[lab] + p.x + p.y;
    }
}

// ---------------- kernel 4: Viterbi decode, one block per batch ----------------
__global__ void k_viterbi(const float* __restrict__ trans, float* __restrict__ out) {
    const int b = blockIdx.x;
    const int tid = threadIdx.x;
    __shared__ float tr[LTOT * LTOT];
    __shared__ float sc[2][LTOT];
    __shared__ unsigned char bp[TT][LTOT];

    for (int l = tid; l < LTOT * LTOT; l += 32) tr[l] = trans[l];
    if (tid < LTOT) sc[0][tid] = (tid == START_LBL) ? 0.0f : LOW_POT;
    __syncwarp();

    const float* un = g_unary + (size_t)b * TT * NLBL;
    for (int t = 0; t < TT; t++) {
        const int cur = t & 1, nxt = cur ^ 1;
        if (tid < LTOT) {
            const int jl = tid;
            float best = -3.4e38f;
            int bi = 0;
#pragma unroll
            for (int p = 0; p < LTOT; p++) {
                float v = sc[cur][p] + tr[jl * LTOT + p];
                if (v > best) { best = v; bi = p; }
            }
            float u = (jl < NLBL) ? un[t * NLBL + jl] : LOW_POT;
            sc[nxt][jl] = best + u;
            bp[t][jl] = (unsigned char)bi;
        }
        __syncwarp();
    }
    if (tid == 0) {
        float best = -3.4e38f;
        int bi = 0;
        for (int jl = 0; jl < LTOT; jl++) {
            float v = sc[0][jl] + tr[END_LBL * LTOT + jl];
            if (v > best) { best = v; bi = jl; }
        }
        out[b] = best;
        int lab = bi;
        for (int t = TT - 1; t >= 0; t--) {
            out[BB + b * TT + t] = (float)lab;
            lab = bp[t][lab];
        }
    }
}

// ---------------- launch ----------------
extern "C" void kernel_launch(void* const* d_in, const int* in_sizes, int n_in,
                              void* d_out, int out_size) {
    const int*   x     = (const int*)d_in[0];
    const float* emb   = (const float*)d_in[1];
    const float* Wihf  = (const float*)d_in[2];
    const float* Whhf  = (const float*)d_in[3];
    const float* bf    = (const float*)d_in[4];
    const float* Wihb  = (const float*)d_in[5];
    const float* Whhb  = (const float*)d_in[6];
    const float* bb    = (const float*)d_in[7];
    const float* fc1W  = (const float*)d_in[8];
    const float* fc1b  = (const float*)d_in[9];
    const float* clsW  = (const float*)d_in[10];
    const float* clsb  = (const float*)d_in[11];
    const float* trans = (const float*)d_in[12];
    float* out = (float*)d_out;

    cudaFuncSetAttribute(k_lstm, cudaFuncAttributeMaxDynamicSharedMemorySize,
                         LSTM_SMEM_FLOATS * sizeof(float));
    cudaFuncSetAttribute(k_fc, cudaFuncAttributeMaxDynamicSharedMemorySize,
                         FC_SMEM_FLOATS * sizeof(float));

    k_init<<<32, 256>>>();
    k_xproj<<<dim3(16, 128), 256>>>(x, emb, Wihf, Wihb, bf, bb);
    k_lstm<<<128, 256, LSTM_SMEM_FLOATS * sizeof(float)>>>(Whhf, Whhb);
    k_fc<<<128, 256, FC_SMEM_FLOATS * sizeof(float)>>>(fc1W, fc1b, clsW, clsb);
    k_viterbi<<<BB, 32>>>(trans, out);
}